// round 15
// baseline (speedup 1.0000x reference)
#include <cuda_runtime.h>
#include <math.h>

typedef unsigned long long ull;

// ---------------- device scratch (no allocations allowed) ----------------
__device__ __align__(16) float g_sub[256];
__device__ __align__(16) float g_gi0[768];
__device__ __align__(16) float g_gh0[768];
__device__ __align__(16) float g_gi[768];          // gi = r0 @ W_ih^T + b_ih
__device__ __align__(16) float g_gh[1024 * 768];   // per-relation gh table
__device__ __align__(16) float g_obj[1024 * 256];  // per-relation obj table

// self-resetting grid barrier (generation counter monotone across graph replays)
__device__ unsigned g_barCnt[4] = {0, 0, 0, 0};
__device__ volatile unsigned g_barGen[4] = {0, 0, 0, 0};

#define CHAIN_BLOCKS 128

__device__ __forceinline__ void gridbar(int id, unsigned nb) {
    __syncthreads();
    if (threadIdx.x == 0) {
        __threadfence();
        unsigned gen = g_barGen[id];
        unsigned old = atomicAdd(&g_barCnt[id], 1u);
        if (old == nb - 1) {
            g_barCnt[id] = 0;
            __threadfence();
            g_barGen[id] = gen + 1;
        } else {
            while (g_barGen[id] == gen) { }
        }
        __threadfence();
    }
    __syncthreads();
}

__device__ __forceinline__ float warp_reduce(float v) {
#pragma unroll
    for (int o = 16; o; o >>= 1) v += __shfl_xor_sync(0xffffffffu, v, o);
    return v;
}
__device__ __forceinline__ float sigmoidf_(float x) { return 1.0f / (1.0f + expf(-x)); }

// packed fp32x2 FMA (2x FFMA rate on sm_103a; only reachable via PTX)
#define FMA2(c, a, b) asm("fma.rn.f32x2 %0, %1, %2, %0;" : "+l"(c) : "l"(a), "l"(b))
#define PACK2(x, y) (((ull)__float_as_uint(y) << 32) | (ull)__float_as_uint(x))

__device__ __forceinline__ float warp_dot256(const float4* __restrict__ x4,
                                             const float4* __restrict__ w4, int lane) {
    float acc = 0.f;
#pragma unroll
    for (int i = 0; i < 2; i++) {
        float4 a = x4[lane + 32 * i];
        float4 b = w4[lane + 32 * i];
        acc += a.x * b.x; acc += a.y * b.y; acc += a.z * b.z; acc += a.w * b.w;
    }
    return warp_reduce(acc);
}

// dynamic smem: sh_b ull[16][129] (16512 B) + union{ sh_a float[16][32] | rj float[16][256] }
#define SM_B_OFF 0
#define SM_X_OFF 16512
#define FUSED_SMEM (16512 + 16384)   // 32896 B < 48KB default

// ============ MEGA: table (bids 0..127) + ent-only scatter (bids >= 128) ============
__global__ __launch_bounds__(256, 5) void kmega(
    const float* __restrict__ enc,  const float* __restrict__ mask,
    const float* __restrict__ subW, const float* __restrict__ subb,
    const float* __restrict__ Wih,  const float* __restrict__ bih,
    const float* __restrict__ Whh,  const float* __restrict__ bhh,
    const float* __restrict__ relT,
    const float* __restrict__ objW, const float* __restrict__ objb,
    const int* __restrict__ seedp,
    const float* __restrict__ ent,
    const int* __restrict__ rel_ids, const int* __restrict__ tail_ids,
    const int* __restrict__ st, const int* __restrict__ orig,
    float* __restrict__ out, int R, int numChunks, int E) {
    extern __shared__ char sm[];
    int tid = threadIdx.x;
    int bid = blockIdx.x;

    if (bid >= CHAIN_BLOCKS) {
        // -------- ent scatter: 8 warps/block, 4 edges/warp, st==1 only --------
        int w = (bid - CHAIN_BLOCKS) * 8 + (tid >> 5);
        int lane = tid & 31;
        int e0 = w * 4;
        if (e0 >= E) return;
        int n = (e0 + 4 <= E) ? 4 : (E - e0);
#pragma unroll
        for (int i = 0; i < 4; i++) {
            if (i >= n) break;
            int e = e0 + i;
            if (st[e] != 1) continue;
            const float4* src = (const float4*)(ent + (size_t)orig[e] * 256);
            float4 a = __ldcs(src + lane);
            float4 b = __ldcs(src + lane + 32);
            float4* dst = (float4*)(out + (size_t)tail_ids[e] * 256);
            __stcs(dst + lane, a);
            __stcs(dst + lane + 32, b);
        }
        return;
    }

    // ================= table path (128 co-resident blocks) =================
    __shared__ float s_x[256];
    int lane = tid & 31;
    int gw = (int)((bid * 256u + tid) >> 5);  // 0..1023

    // ---- chain stage 1: sub (256 dots) + gi0 (768 dots) ----
    {
        const float4* x4;
        const float4* w4;
        if (gw < 256) { x4 = (const float4*)mask; w4 = (const float4*)(subW + (size_t)gw * 256); }
        else          { x4 = (const float4*)enc;  w4 = (const float4*)(Wih + (size_t)(gw - 256) * 256); }
        float acc = warp_dot256(x4, w4, lane);
        if (lane == 0) {
            if (gw < 256) g_sub[gw] = tanhf(acc + subb[gw]);
            else          g_gi0[gw - 256] = acc + bih[gw - 256];
        }
    }
    gridbar(0, CHAIN_BLOCKS);

    // ---- chain stage 2: gh0 = sub @ Whh^T + bhh ----
    s_x[tid] = g_sub[tid];
    __syncthreads();
    if (gw < 768) {
        float acc = warp_dot256((const float4*)s_x, (const float4*)(Whh + (size_t)gw * 256), lane);
        if (lane == 0) g_gh0[gw] = acc + bhh[gw];
    }
    gridbar(1, CHAIN_BLOCKS);

    // ---- chain stage 3: r0 gates, gi = r0 @ Wih^T + bih ----
    {
        int d = tid;
        float r = sigmoidf_(g_gi0[d] + g_gh0[d]);
        float z = sigmoidf_(g_gi0[256 + d] + g_gh0[256 + d]);
        float n = tanhf(g_gi0[512 + d] + r * g_gh0[512 + d]);
        float h = g_sub[d];
        float r0 = (1.f - z) * n + z * h;
        if (bid == 0) out[(size_t)seedp[0] * 256 + d] = h;  // out[seed] = sub
        __syncthreads();
        s_x[d] = r0;
    }
    __syncthreads();
    if (gw < 768) {
        float acc = warp_dot256((const float4*)s_x, (const float4*)(Wih + (size_t)gw * 256), lane);
        if (lane == 0) g_gi[gw] = acc + bih[gw];
    }

    // ---- phase B: gh GEMM tiles (16 rels x 128 cols, k-chunks of 32) ----
    ull (*sh_b)[129] = (ull(*)[129])(sm + SM_B_OFF);
    float* sh_a = (float*)(sm + SM_X_OFF);           // [16][32]
    int tx = tid & 63;
    int ty = tid >> 6;

    int numTiles = 6 * numChunks;
#pragma unroll 1
    for (int t = bid; t < numTiles; t += CHAIN_BLOCKS) {
        int chunk = t / 6, jc = t % 6;
        int relBase = chunk * 16, jBase = jc * 128;
        ull c[4][2] = {};
#pragma unroll 1
        for (int kc = 0; kc < 256; kc += 32) {
            if (tid < 128) {
                int row = tid >> 3, f4 = tid & 7;
                int rel = relBase + row; if (rel >= R) rel = R - 1;
                *((float4*)(sh_a + row * 32) + f4) =
                    *((const float4*)(relT + (size_t)rel * 256 + kc) + f4);
            }
#pragma unroll
            for (int i = 0; i < 4; i++) {
                int idx = tid + 256 * i;
                int jrow = idx >> 3, f4 = idx & 7;
                float4 v = *(const float4*)(Whh + (size_t)(jBase + jrow) * 256 + kc + f4 * 4);
                sh_b[f4 * 2][jrow]     = PACK2(v.x, v.y);
                sh_b[f4 * 2 + 1][jrow] = PACK2(v.z, v.w);
            }
            __syncthreads();
            const ull* a0 = (const ull*)(sh_a + (4 * ty + 0) * 32);
            const ull* a1 = (const ull*)(sh_a + (4 * ty + 1) * 32);
            const ull* a2 = (const ull*)(sh_a + (4 * ty + 2) * 32);
            const ull* a3 = (const ull*)(sh_a + (4 * ty + 3) * 32);
#pragma unroll
            for (int k2 = 0; k2 < 16; k2++) {
                ull w0 = sh_b[k2][tx];
                ull w1 = sh_b[k2][tx + 64];
                ull h;
                h = a0[k2]; FMA2(c[0][0], h, w0); FMA2(c[0][1], h, w1);
                h = a1[k2]; FMA2(c[1][0], h, w0); FMA2(c[1][1], h, w1);
                h = a2[k2]; FMA2(c[2][0], h, w0); FMA2(c[2][1], h, w1);
                h = a3[k2]; FMA2(c[3][0], h, w0); FMA2(c[3][1], h, w1);
            }
            __syncthreads();
        }
#pragma unroll
        for (int a = 0; a < 4; a++) {
            int rel = relBase + 4 * ty + a;
            if (rel >= R) continue;
#pragma unroll
            for (int jj = 0; jj < 2; jj++) {
                int j = jBase + tx + jj * 64;
                float lo = __uint_as_float((unsigned)(c[a][jj] & 0xffffffffu));
                float hi = __uint_as_float((unsigned)(c[a][jj] >> 32));
                g_gh[(size_t)rel * 768 + j] = lo + hi + bhh[j];
            }
        }
    }
    gridbar(3, CHAIN_BLOCKS);   // gh + gi fully visible

    // ---- phase C: finisher per chunk: gates -> rj(smem) -> obj GEMM ----
    float* rj = (float*)(sm + SM_X_OFF);             // [16][256]
#pragma unroll 1
    for (int chunk = bid; chunk < numChunks; chunk += CHAIN_BLOCKS) {
        int relBase = chunk * 16;
#pragma unroll 1
        for (int i = 0; i < 16; i++) {
            int idx = tid + 256 * i;
            int rr = idx >> 8, d = idx & 255;
            int rel = relBase + rr;
            int relc = rel < R ? rel : R - 1;
            const float* gh = g_gh + (size_t)relc * 768;
            float r = sigmoidf_(g_gi[d] + gh[d]);
            float z = sigmoidf_(g_gi[256 + d] + gh[256 + d]);
            float n = tanhf(g_gi[512 + d] + r * gh[512 + d]);
            float h = relT[(size_t)relc * 256 + d];
            rj[rr * 256 + d] = (1.f - z) * n + z * h;
        }
        __syncthreads();

#pragma unroll 1
        for (int jc = 0; jc < 2; jc++) {
            int jBase = jc * 128;
            ull c[4][2] = {};
#pragma unroll 1
            for (int kc = 0; kc < 256; kc += 32) {
#pragma unroll
                for (int i = 0; i < 4; i++) {
                    int idx = tid + 256 * i;
                    int jrow = idx >> 3, f4 = idx & 7;
                    float4 v = *(const float4*)(objW + (size_t)(jBase + jrow) * 256 + kc + f4 * 4);
                    sh_b[f4 * 2][jrow]     = PACK2(v.x, v.y);
                    sh_b[f4 * 2 + 1][jrow] = PACK2(v.z, v.w);
                }
                __syncthreads();
                const ull* a0 = (const ull*)(rj + (4 * ty + 0) * 256 + kc);
                const ull* a1 = (const ull*)(rj + (4 * ty + 1) * 256 + kc);
                const ull* a2 = (const ull*)(rj + (4 * ty + 2) * 256 + kc);
                const ull* a3 = (const ull*)(rj + (4 * ty + 3) * 256 + kc);
#pragma unroll
                for (int k2 = 0; k2 < 16; k2++) {
                    ull w0 = sh_b[k2][tx];
                    ull w1 = sh_b[k2][tx + 64];
                    ull h;
                    h = a0[k2]; FMA2(c[0][0], h, w0); FMA2(c[0][1], h, w1);
                    h = a1[k2]; FMA2(c[1][0], h, w0); FMA2(c[1][1], h, w1);
                    h = a2[k2]; FMA2(c[2][0], h, w0); FMA2(c[2][1], h, w1);
                    h = a3[k2]; FMA2(c[3][0], h, w0); FMA2(c[3][1], h, w1);
                }
                __syncthreads();
            }
#pragma unroll
            for (int a = 0; a < 4; a++) {
                int rel = relBase + 4 * ty + a;
                if (rel >= R) continue;
#pragma unroll
                for (int jj = 0; jj < 2; jj++) {
                    int j = jBase + tx + jj * 64;
                    float lo = __uint_as_float((unsigned)(c[a][jj] & 0xffffffffu));
                    float hi = __uint_as_float((unsigned)(c[a][jj] >> 32));
                    g_obj[(size_t)rel * 256 + j] = tanhf(lo + hi + objb[j]);
                }
            }
        }
        __syncthreads();   // protect rj before next chunk reuse
    }
}

// ---------------- KOBJ: st==0 edges, source = g_obj (L2-resident), write-bound ---------
__global__ __launch_bounds__(256) void kobj(const int* __restrict__ rel_ids,
                                            const int* __restrict__ tail_ids,
                                            const int* __restrict__ st,
                                            float* __restrict__ out, int E) {
    int w = (blockIdx.x * 256 + threadIdx.x) >> 5;
    int lane = threadIdx.x & 31;
    int e0 = w * 4;
    if (e0 >= E) return;
    int n = (e0 + 4 <= E) ? 4 : (E - e0);
#pragma unroll
    for (int i = 0; i < 4; i++) {
        if (i >= n) break;
        int e = e0 + i;
        if (st[e] == 1) continue;
        const float4* src = (const float4*)(g_obj + (size_t)rel_ids[e] * 256);
        float4 a = __ldg(src + lane);
        float4 b = __ldg(src + lane + 32);
        float4* dst = (float4*)(out + (size_t)tail_ids[e] * 256);
        __stcs(dst + lane, a);
        __stcs(dst + lane + 32, b);
    }
}

// ---------------- launch ----------------
extern "C" void kernel_launch(void* const* d_in, const int* in_sizes, int n_in,
                              void* d_out, int out_size) {
    const float* enc   = (const float*)d_in[0];
    const float* mask  = (const float*)d_in[1];
    const float* ent   = (const float*)d_in[2];
    const float* relT  = (const float*)d_in[3];
    const float* Wih   = (const float*)d_in[4];
    const float* Whh   = (const float*)d_in[5];
    const float* bih   = (const float*)d_in[6];
    const float* bhh   = (const float*)d_in[7];
    const float* subW  = (const float*)d_in[8];
    const float* subb  = (const float*)d_in[9];
    const float* objW  = (const float*)d_in[10];
    const float* objb  = (const float*)d_in[11];
    const int* rel_ids  = (const int*)d_in[12];
    const int* tail_ids = (const int*)d_in[13];
    const int* tstate   = (const int*)d_in[14];
    const int* orig     = (const int*)d_in[15];
    const int* seedp    = (const int*)d_in[16];
    float* out = (float*)d_out;

    int E = in_sizes[12];
    int R = in_sizes[3] / 256;
    if (R > 1024) R = 1024;
    int numChunks = (R + 15) / 16;              // <= 64

    int scatterWarps = (E + 3) / 4;
    int scatterBlocks = (scatterWarps + 7) / 8;

    // 1) mega: table (128 blocks) + ent-only scatter, overlapped in one launch
    kmega<<<CHAIN_BLOCKS + scatterBlocks, 256, FUSED_SMEM>>>(
        enc, mask, subW, subb, Wih, bih, Whh, bhh, relT, objW, objb, seedp,
        ent, rel_ids, tail_ids, tstate, orig, out, R, numChunks, E);

    // 2) obj scatter (table ready; source in L2, write-bound)
    kobj<<<scatterBlocks, 256>>>(rel_ids, tail_ids, tstate, out, E);
}

// round 16
// speedup vs baseline: 1.1945x; 1.1945x over previous
#include <cuda_runtime.h>
#include <math.h>

typedef unsigned long long ull;

// ---------------- device scratch (no allocations allowed) ----------------
__device__ __align__(16) float g_sub[256];
__device__ __align__(16) float g_gi0[768];
__device__ __align__(16) float g_gh0[768];
__device__ __align__(16) float g_gi[768];          // gi = r0 @ W_ih^T + b_ih
__device__ __align__(16) float g_gh[1024 * 768];   // per-relation gh table
__device__ __align__(16) float g_obj[1024 * 256];  // per-relation obj table

// self-resetting grid barrier (generation counter monotone across graph replays)
__device__ unsigned g_barCnt[4] = {0, 0, 0, 0};
__device__ volatile unsigned g_barGen[4] = {0, 0, 0, 0};

#define CHAIN_BLOCKS 128

__device__ __forceinline__ void gridbar(int id, unsigned nb) {
    __syncthreads();
    if (threadIdx.x == 0) {
        __threadfence();
        unsigned gen = g_barGen[id];
        unsigned old = atomicAdd(&g_barCnt[id], 1u);
        if (old == nb - 1) {
            g_barCnt[id] = 0;
            __threadfence();
            g_barGen[id] = gen + 1;
        } else {
            while (g_barGen[id] == gen) { }
        }
        __threadfence();
    }
    __syncthreads();
}

__device__ __forceinline__ float warp_reduce(float v) {
#pragma unroll
    for (int o = 16; o; o >>= 1) v += __shfl_xor_sync(0xffffffffu, v, o);
    return v;
}
__device__ __forceinline__ float sigmoidf_(float x) { return 1.0f / (1.0f + expf(-x)); }

// packed fp32x2 FMA (2x FFMA rate on sm_103a; only reachable via PTX)
#define FMA2(c, a, b) asm("fma.rn.f32x2 %0, %1, %2, %0;" : "+l"(c) : "l"(a), "l"(b))
#define PACK2(x, y) (((ull)__float_as_uint(y) << 32) | (ull)__float_as_uint(x))

__device__ __forceinline__ float warp_dot256(const float4* __restrict__ x4,
                                             const float4* __restrict__ w4, int lane) {
    float acc = 0.f;
#pragma unroll
    for (int i = 0; i < 2; i++) {
        float4 a = x4[lane + 32 * i];
        float4 b = w4[lane + 32 * i];
        acc += a.x * b.x; acc += a.y * b.y; acc += a.z * b.z; acc += a.w * b.w;
    }
    return warp_reduce(acc);
}

// ============ KPAR: chain (bids 0..127, co-resident) || gh GEMM tiles (bids >=128) ======
// gh = relT @ Whh^T + bhh is INDEPENDENT of the chain, so the two run concurrently.
__global__ __launch_bounds__(256) void kpar(const float* __restrict__ enc,
                                            const float* __restrict__ mask,
                                            const float* __restrict__ subW,
                                            const float* __restrict__ subb,
                                            const float* __restrict__ Wih,
                                            const float* __restrict__ bih,
                                            const float* __restrict__ Whh,
                                            const float* __restrict__ bhh,
                                            const float* __restrict__ relT,
                                            const int* __restrict__ seedp,
                                            float* __restrict__ out,
                                            int R) {
    __shared__ float sh_a[16][64];        // gemm A tile (also unused by chain)
    __shared__ ull sh_b[32][129];         // gemm B tile
    __shared__ float s_x[256];            // chain vector

    int tid = threadIdx.x;
    int bid = blockIdx.x;

    if (bid < CHAIN_BLOCKS) {
        // ---------------- seed GRU chain ----------------
        int lane = tid & 31;
        int gw = (int)((bid * 256u + tid) >> 5);  // 0..1023

        {   // stage 1: sub (256 dots) + gi0 (768 dots)
            const float4* x4;
            const float4* w4;
            if (gw < 256) { x4 = (const float4*)mask; w4 = (const float4*)(subW + (size_t)gw * 256); }
            else          { x4 = (const float4*)enc;  w4 = (const float4*)(Wih + (size_t)(gw - 256) * 256); }
            float acc = warp_dot256(x4, w4, lane);
            if (lane == 0) {
                if (gw < 256) g_sub[gw] = tanhf(acc + subb[gw]);
                else          g_gi0[gw - 256] = acc + bih[gw - 256];
            }
        }
        gridbar(0, CHAIN_BLOCKS);

        // stage 2: gh0 = sub @ Whh^T + bhh
        s_x[tid] = g_sub[tid];
        __syncthreads();
        if (gw < 768) {
            float acc = warp_dot256((const float4*)s_x, (const float4*)(Whh + (size_t)gw * 256), lane);
            if (lane == 0) g_gh0[gw] = acc + bhh[gw];
        }
        gridbar(1, CHAIN_BLOCKS);

        // stage 3: r0 gates (per-block redundant), gi = r0 @ Wih^T + bih
        {
            int d = tid;
            float r = sigmoidf_(g_gi0[d] + g_gh0[d]);
            float z = sigmoidf_(g_gi0[256 + d] + g_gh0[256 + d]);
            float n = tanhf(g_gi0[512 + d] + r * g_gh0[512 + d]);
            float h = g_sub[d];
            float r0 = (1.f - z) * n + z * h;
            if (bid == 0) out[(size_t)seedp[0] * 256 + d] = h;  // out[seed] = sub
            __syncthreads();
            s_x[d] = r0;
        }
        __syncthreads();
        if (gw < 768) {
            float acc = warp_dot256((const float4*)s_x, (const float4*)(Wih + (size_t)gw * 256), lane);
            if (lane == 0) g_gi[gw] = acc + bih[gw];
        }
        return;
    }

    // ---------------- gh GEMM tile: 16 rels x 128 cols, prefetch, kc=64 ----------------
    int tile = bid - CHAIN_BLOCKS;
    int chunk = tile / 6;
    int jc = tile % 6;
    int relBase = chunk * 16;
    int jBase = jc * 128;
    int tx = tid & 63;
    int ty = tid >> 6;

    int arow = tid >> 4, af4 = tid & 15;
    int rel0 = relBase + arow; if (rel0 >= R) rel0 = R - 1;
    const float4* Abase = (const float4*)(relT + (size_t)rel0 * 256);

    float4 pa = Abase[af4];
    float4 pb[8];
#pragma unroll
    for (int i = 0; i < 8; i++) {
        int idx = tid + 256 * i;
        int jrow = idx >> 4, f4 = idx & 15;
        pb[i] = *(const float4*)(Whh + (size_t)(jBase + jrow) * 256 + f4 * 4);
    }

    ull c[4][2] = {};

#pragma unroll 1
    for (int kc = 0; kc < 256; kc += 64) {
        *((float4*)sh_a[arow] + af4) = pa;
#pragma unroll
        for (int i = 0; i < 8; i++) {
            int idx = tid + 256 * i;
            int jrow = idx >> 4, f4 = idx & 15;
            sh_b[f4 * 2][jrow]     = PACK2(pb[i].x, pb[i].y);
            sh_b[f4 * 2 + 1][jrow] = PACK2(pb[i].z, pb[i].w);
        }
        __syncthreads();

        if (kc < 192) {
            pa = Abase[af4 + (kc + 64) / 4];
#pragma unroll
            for (int i = 0; i < 8; i++) {
                int idx = tid + 256 * i;
                int jrow = idx >> 4, f4 = idx & 15;
                pb[i] = *(const float4*)(Whh + (size_t)(jBase + jrow) * 256 + kc + 64 + f4 * 4);
            }
        }

        const ull* a0 = (const ull*)sh_a[4 * ty + 0];
        const ull* a1 = (const ull*)sh_a[4 * ty + 1];
        const ull* a2 = (const ull*)sh_a[4 * ty + 2];
        const ull* a3 = (const ull*)sh_a[4 * ty + 3];
#pragma unroll
        for (int k2 = 0; k2 < 32; k2++) {
            ull w0 = sh_b[k2][tx];
            ull w1 = sh_b[k2][tx + 64];
            ull h;
            h = a0[k2]; FMA2(c[0][0], h, w0); FMA2(c[0][1], h, w1);
            h = a1[k2]; FMA2(c[1][0], h, w0); FMA2(c[1][1], h, w1);
            h = a2[k2]; FMA2(c[2][0], h, w0); FMA2(c[2][1], h, w1);
            h = a3[k2]; FMA2(c[3][0], h, w0); FMA2(c[3][1], h, w1);
        }
        __syncthreads();
    }

#pragma unroll
    for (int a = 0; a < 4; a++) {
        int rel = relBase + 4 * ty + a;
        if (rel >= R) continue;
#pragma unroll
        for (int jj = 0; jj < 2; jj++) {
            int j = jBase + tx + jj * 64;
            float lo = __uint_as_float((unsigned)(c[a][jj] & 0xffffffffu));
            float hi = __uint_as_float((unsigned)(c[a][jj] >> 32));
            g_gh[(size_t)rel * 768 + j] = lo + hi + bhh[j];
        }
    }
}

// ============ KFIN: gates (fused) + obj GEMM. grid (2 jc, numChunks) ============
// Each block: rj[16][256] = GRU gates for its 16 relations (redundant across the 2 jc
// blocks — trivial arithmetic), then its 16x128 obj tile with prefetch.
#define FIN_SMEM (16384 + 33024)   // rj + sh_b

__global__ __launch_bounds__(256) void kfin(const float* __restrict__ relT,
                                            const float* __restrict__ objW,
                                            const float* __restrict__ objb,
                                            int R) {
    extern __shared__ char sm[];
    float* rj = (float*)sm;                         // [16][256]
    ull (*sh_b)[129] = (ull(*)[129])(sm + 16384);   // [32][129]

    int tid = threadIdx.x;
    int chunk = blockIdx.y;
    int jc = blockIdx.x;
    int relBase = chunk * 16;
    int jBase = jc * 128;
    int tx = tid & 63;
    int ty = tid >> 6;

    // prefetch first objW tile while computing gates
    float4 pb[8];
#pragma unroll
    for (int i = 0; i < 8; i++) {
        int idx = tid + 256 * i;
        int jrow = idx >> 4, f4 = idx & 15;
        pb[i] = *(const float4*)(objW + (size_t)(jBase + jrow) * 256 + f4 * 4);
    }

    // gates: 16 relations x 256 dims
#pragma unroll 1
    for (int i = 0; i < 16; i++) {
        int idx = tid + 256 * i;
        int rr = idx >> 8, d = idx & 255;
        int rel = relBase + rr;
        int relc = rel < R ? rel : R - 1;
        const float* gh = g_gh + (size_t)relc * 768;
        float r = sigmoidf_(g_gi[d] + gh[d]);
        float z = sigmoidf_(g_gi[256 + d] + gh[256 + d]);
        float n = tanhf(g_gi[512 + d] + r * gh[512 + d]);
        float h = relT[(size_t)relc * 256 + d];
        rj[rr * 256 + d] = (1.f - z) * n + z * h;
    }
    __syncthreads();

    ull c[4][2] = {};

#pragma unroll 1
    for (int kc = 0; kc < 256; kc += 64) {
#pragma unroll
        for (int i = 0; i < 8; i++) {
            int idx = tid + 256 * i;
            int jrow = idx >> 4, f4 = idx & 15;
            sh_b[f4 * 2][jrow]     = PACK2(pb[i].x, pb[i].y);
            sh_b[f4 * 2 + 1][jrow] = PACK2(pb[i].z, pb[i].w);
        }
        __syncthreads();

        if (kc < 192) {
#pragma unroll
            for (int i = 0; i < 8; i++) {
                int idx = tid + 256 * i;
                int jrow = idx >> 4, f4 = idx & 15;
                pb[i] = *(const float4*)(objW + (size_t)(jBase + jrow) * 256 + kc + 64 + f4 * 4);
            }
        }

        const ull* a0 = (const ull*)(rj + (4 * ty + 0) * 256 + kc);
        const ull* a1 = (const ull*)(rj + (4 * ty + 1) * 256 + kc);
        const ull* a2 = (const ull*)(rj + (4 * ty + 2) * 256 + kc);
        const ull* a3 = (const ull*)(rj + (4 * ty + 3) * 256 + kc);
#pragma unroll
        for (int k2 = 0; k2 < 32; k2++) {
            ull w0 = sh_b[k2][tx];
            ull w1 = sh_b[k2][tx + 64];
            ull h;
            h = a0[k2]; FMA2(c[0][0], h, w0); FMA2(c[0][1], h, w1);
            h = a1[k2]; FMA2(c[1][0], h, w0); FMA2(c[1][1], h, w1);
            h = a2[k2]; FMA2(c[2][0], h, w0); FMA2(c[2][1], h, w1);
            h = a3[k2]; FMA2(c[3][0], h, w0); FMA2(c[3][1], h, w1);
        }
        __syncthreads();
    }

#pragma unroll
    for (int a = 0; a < 4; a++) {
        int rel = relBase + 4 * ty + a;
        if (rel >= R) continue;
#pragma unroll
        for (int jj = 0; jj < 2; jj++) {
            int j = jBase + tx + jj * 64;
            float lo = __uint_as_float((unsigned)(c[a][jj] & 0xffffffffu));
            float hi = __uint_as_float((unsigned)(c[a][jj] >> 32));
            g_obj[(size_t)rel * 256 + j] = tanhf(lo + hi + objb[j]);
        }
    }
}

// ---------------- K6: per-edge gather/scatter (measured-best form, 57us) ----------------
__global__ __launch_bounds__(256) void k6(const float* __restrict__ ent,
                                          const int* __restrict__ rel_ids,
                                          const int* __restrict__ tail_ids,
                                          const int* __restrict__ st,
                                          const int* __restrict__ orig,
                                          float* __restrict__ out, int E) {
    int w = (blockIdx.x * 256 + threadIdx.x) >> 5;
    int lane = threadIdx.x & 31;
    if (w >= E) return;
    float4* dst = (float4*)(out + (size_t)tail_ids[w] * 256);
    if (st[w] == 1) {
        const float4* src = (const float4*)(ent + (size_t)orig[w] * 256);
        float4 a = __ldcs(src + lane);
        float4 b = __ldcs(src + lane + 32);
        __stcs(dst + lane, a);
        __stcs(dst + lane + 32, b);
    } else {
        const float4* src = (const float4*)(g_obj + (size_t)rel_ids[w] * 256);
        float4 a = __ldg(src + lane);
        float4 b = __ldg(src + lane + 32);
        __stcs(dst + lane, a);
        __stcs(dst + lane + 32, b);
    }
}

// ---------------- launch ----------------
extern "C" void kernel_launch(void* const* d_in, const int* in_sizes, int n_in,
                              void* d_out, int out_size) {
    const float* enc   = (const float*)d_in[0];
    const float* mask  = (const float*)d_in[1];
    const float* ent   = (const float*)d_in[2];
    const float* relT  = (const float*)d_in[3];
    const float* Wih   = (const float*)d_in[4];
    const float* Whh   = (const float*)d_in[5];
    const float* bih   = (const float*)d_in[6];
    const float* bhh   = (const float*)d_in[7];
    const float* subW  = (const float*)d_in[8];
    const float* subb  = (const float*)d_in[9];
    const float* objW  = (const float*)d_in[10];
    const float* objb  = (const float*)d_in[11];
    const int* rel_ids  = (const int*)d_in[12];
    const int* tail_ids = (const int*)d_in[13];
    const int* tstate   = (const int*)d_in[14];
    const int* orig     = (const int*)d_in[15];
    const int* seedp    = (const int*)d_in[16];
    float* out = (float*)d_out;

    int E = in_sizes[12];
    int R = in_sizes[3] / 256;
    if (R > 1024) R = 1024;
    int numChunks = (R + 15) / 16;              // <= 64

    static bool attr_done = false;
    if (!attr_done) {
        cudaFuncSetAttribute(kfin, cudaFuncAttributeMaxDynamicSharedMemorySize, FIN_SMEM);
        attr_done = true;
    }

    // 1) chain || gh GEMM (independent; chain blocks first wave, barriers safe)
    kpar<<<CHAIN_BLOCKS + 6 * numChunks, 256>>>(enc, mask, subW, subb, Wih, bih,
                                                Whh, bhh, relT, seedp, out, R);

    // 2) fused gates + obj GEMM
    dim3 fin_grid(2, (unsigned)numChunks);
    kfin<<<fin_grid, 256, FIN_SMEM>>>(relT, objW, objb, R);

    // 3) main scatter
    int blocks = (E + 7) / 8;
    k6<<<blocks, 256>>>(ent, rel_ids, tail_ids, tstate, orig, out, E);
}